// round 4
// baseline (speedup 1.0000x reference)
#include <cuda_runtime.h>
#include <math.h>

// Problem constants
#define B_ 2
#define T_ 8192
#define H_ 16
#define NB_ 32
#define CH 512              // H*NB
#define D_ 1024
#define DH_ 128
#define M_ (B_*T_)          // 16384 rows
#define LCH 128             // scan chunk length
#define NCHUNK (T_/LCH)     // 64 chunks

#define PI_F  3.14159265358979323846f
#define TWOPI_F 6.283185307179586f

// ---------------- scratch (static device globals; no runtime alloc) --------
__device__ float g_hid[(size_t)M_*DH_];     // 8 MB
__device__ float g_nu [(size_t)M_*CH];      // 33.5 MB
__device__ float g_K[CH];
__device__ float g_alpha[CH];
__device__ float g_carry[B_*NCHUNK*CH];     // 256 KB

// ============================================================================
// GEMM1 + exact GELU:  hid = gelu(X @ W1 + b1)
// X: [M,1024], W1: [1024,128], hid: [M,128]
// BM=64, BN=128, BK=16, 256 threads (16x16), micro-tile TM=4 x TN=8
// ============================================================================
__global__ __launch_bounds__(256) void gemm1_gelu_kernel(
    const float* __restrict__ A, const float* __restrict__ W,
    const float* __restrict__ bias)
{
    __shared__ float As[16][68];   // [k][m], padded: 68*4=272B, 16B aligned
    __shared__ float Bs[16][128];  // [k][n]

    const int tid = threadIdx.x;
    const int tx = tid & 15;       // 0..15  -> cols tx*8..tx*8+7
    const int ty = tid >> 4;       // 0..15  -> rows ty*4..ty*4+3
    const int m0 = blockIdx.x * 64;

    // A tile load mapping: each thread loads one float4 (row, 4 k's)
    const int arow = tid >> 2;          // 0..63
    const int akq  = (tid & 3) * 4;     // 0,4,8,12
    // B tile load mapping: each thread loads 8 floats (one k-row, 8 n's)
    const int bk = tid >> 4;            // 0..15
    const int bn = (tid & 15) * 8;      // 0..120

    float acc[4][8];
    #pragma unroll
    for (int i = 0; i < 4; i++)
        #pragma unroll
        for (int j = 0; j < 8; j++) acc[i][j] = 0.f;

    for (int k0 = 0; k0 < D_; k0 += 16) {
        float4 av = *(const float4*)&A[(size_t)(m0 + arow) * D_ + k0 + akq];
        As[akq + 0][arow] = av.x;
        As[akq + 1][arow] = av.y;
        As[akq + 2][arow] = av.z;
        As[akq + 3][arow] = av.w;

        float4 bv0 = *(const float4*)&W[(size_t)(k0 + bk) * DH_ + bn];
        float4 bv1 = *(const float4*)&W[(size_t)(k0 + bk) * DH_ + bn + 4];
        *(float4*)&Bs[bk][bn]     = bv0;
        *(float4*)&Bs[bk][bn + 4] = bv1;
        __syncthreads();

        #pragma unroll
        for (int kk = 0; kk < 16; kk++) {
            float4 a4 = *(const float4*)&As[kk][ty * 4];
            float4 b0 = *(const float4*)&Bs[kk][tx * 8];
            float4 b1 = *(const float4*)&Bs[kk][tx * 8 + 4];
            const float av_[4] = {a4.x, a4.y, a4.z, a4.w};
            const float bv_[8] = {b0.x, b0.y, b0.z, b0.w, b1.x, b1.y, b1.z, b1.w};
            #pragma unroll
            for (int i = 0; i < 4; i++)
                #pragma unroll
                for (int j = 0; j < 8; j++)
                    acc[i][j] = fmaf(av_[i], bv_[j], acc[i][j]);
        }
        __syncthreads();
    }

    #pragma unroll
    for (int i = 0; i < 4; i++) {
        const int m = m0 + ty * 4 + i;
        #pragma unroll
        for (int j = 0; j < 8; j++) {
            const int n = tx * 8 + j;
            float x = acc[i][j] + bias[n];
            float g = x * normcdff(x);      // exact GELU: x * Phi(x)
            g_hid[(size_t)m * DH_ + n] = g;
        }
    }
}

// ============================================================================
// GEMM2 + tanh + wrap:  nu = wrap(pi*tanh(hid @ W2 + b2) - theta)
// hid: [M,128], W2: [128,512], blocked BN=128 over 4 n-blocks
// ============================================================================
__global__ __launch_bounds__(256) void gemm2_nu_kernel(
    const float* __restrict__ W, const float* __restrict__ bias,
    const float* __restrict__ theta)
{
    __shared__ float As[16][68];
    __shared__ float Bs[16][128];

    const int tid = threadIdx.x;
    const int tx = tid & 15;
    const int ty = tid >> 4;
    const int m0 = blockIdx.x * 64;
    const int n0 = blockIdx.y * 128;

    const int arow = tid >> 2;
    const int akq  = (tid & 3) * 4;
    const int bk = tid >> 4;
    const int bn = (tid & 15) * 8;

    float acc[4][8];
    #pragma unroll
    for (int i = 0; i < 4; i++)
        #pragma unroll
        for (int j = 0; j < 8; j++) acc[i][j] = 0.f;

    for (int k0 = 0; k0 < DH_; k0 += 16) {
        float4 av = *(const float4*)&g_hid[(size_t)(m0 + arow) * DH_ + k0 + akq];
        As[akq + 0][arow] = av.x;
        As[akq + 1][arow] = av.y;
        As[akq + 2][arow] = av.z;
        As[akq + 3][arow] = av.w;

        float4 bv0 = *(const float4*)&W[(size_t)(k0 + bk) * CH + n0 + bn];
        float4 bv1 = *(const float4*)&W[(size_t)(k0 + bk) * CH + n0 + bn + 4];
        *(float4*)&Bs[bk][bn]     = bv0;
        *(float4*)&Bs[bk][bn + 4] = bv1;
        __syncthreads();

        #pragma unroll
        for (int kk = 0; kk < 16; kk++) {
            float4 a4 = *(const float4*)&As[kk][ty * 4];
            float4 b0 = *(const float4*)&Bs[kk][tx * 8];
            float4 b1 = *(const float4*)&Bs[kk][tx * 8 + 4];
            const float av_[4] = {a4.x, a4.y, a4.z, a4.w};
            const float bv_[8] = {b0.x, b0.y, b0.z, b0.w, b1.x, b1.y, b1.z, b1.w};
            #pragma unroll
            for (int i = 0; i < 4; i++)
                #pragma unroll
                for (int j = 0; j < 8; j++)
                    acc[i][j] = fmaf(av_[i], bv_[j], acc[i][j]);
        }
        __syncthreads();
    }

    #pragma unroll
    for (int i = 0; i < 4; i++) {
        const int m = m0 + ty * 4 + i;
        #pragma unroll
        for (int j = 0; j < 8; j++) {
            const int n = n0 + tx * 8 + j;
            float z = PI_F * tanhf(acc[i][j] + bias[n]);
            float diff = z - theta[(size_t)m * CH + n];
            // wrap to (-pi, pi] == atan2(sin, cos)
            float nu = remainderf(diff, TWOPI_F);
            g_nu[(size_t)m * CH + n] = nu;
        }
    }
}

// ============================================================================
// K* closed-form DARE
// ============================================================================
__global__ void kstar_kernel(const float* __restrict__ lq,
                             const float* __restrict__ lr,
                             float* __restrict__ outK, int write_out)
{
    int i = threadIdx.x;
    float Q = expf(lq[i]);
    float R = expf(lr[i]);
    float P_post = 0.5f * (-Q + sqrtf(Q * Q + 4.0f * Q * R));
    float P_pred = P_post + Q;
    float K = P_pred / (P_pred + R);
    g_K[i] = K;
    g_alpha[i] = 1.0f - K;
    if (write_out) outK[i] = K;
}

// ============================================================================
// Scan pass A: per-(b, chunk) local carries (zero-init recurrence over LCH)
// grid: B*NCHUNK blocks x 512 threads (1 thread per channel)
// Loads are fully coalesced: all 512 channels of one t contiguous.
// ============================================================================
__global__ __launch_bounds__(512) void carry_kernel()
{
    const int bx = blockIdx.x;
    const int b = bx / NCHUNK;
    const int j = bx % NCHUNK;
    const int ch = threadIdx.x;
    const float K = g_K[ch];
    const float a = g_alpha[ch];
    const float* nu = g_nu + ((size_t)(b * T_ + j * LCH)) * CH + ch;

    float c = 0.f;
    #pragma unroll 4
    for (int i = 0; i < LCH; i++)
        c = fmaf(a, c, K * nu[(size_t)i * CH]);
    g_carry[(b * NCHUNK + j) * CH + ch] = c;
}

// ============================================================================
// Scan pass B: exact carry combine across chunks with factor alpha^LCH.
// Rewrites g_carry[b][j][ch] to hold the carry-IN (d at t = j*LCH - 1).
// ============================================================================
__global__ __launch_bounds__(512) void combine_kernel()
{
    const int b = blockIdx.x;
    const int ch = threadIdx.x;
    float a = g_alpha[ch];
    float aL = a;
    #pragma unroll
    for (int i = 0; i < 7; i++) aL *= aL;   // alpha^128 (LCH=2^7)

    float s = 0.f;
    for (int j = 0; j < NCHUNK; j++) {
        const int idx = (b * NCHUNK + j) * CH + ch;
        float v = g_carry[idx];
        g_carry[idx] = s;           // carry-in for chunk j
        s = fmaf(aL, s, v);
    }
}

// ============================================================================
// Scan pass C: final recurrence from exact carry-in; write theta_hat and d
// ============================================================================
__global__ __launch_bounds__(512) void final_kernel(
    const float* __restrict__ theta, float* __restrict__ out, int write_d)
{
    const int bx = blockIdx.x;
    const int b = bx / NCHUNK;
    const int j = bx % NCHUNK;
    const int ch = threadIdx.x;
    const float K = g_K[ch];
    const float a = g_alpha[ch];

    float d = g_carry[(b * NCHUNK + j) * CH + ch];
    const size_t base = ((size_t)(b * T_ + j * LCH)) * CH + ch;

    #pragma unroll 4
    for (int i = 0; i < LCH; i++) {
        const size_t idx = base + (size_t)i * CH;
        d = fmaf(a, d, K * g_nu[idx]);
        out[idx] = theta[idx] + d;                      // theta_hat
        if (write_d) out[(size_t)M_ * CH + idx] = d;    // d
    }
}

// ============================================================================
// Launch
// Inputs (metadata order): theta_path, content_emb, W1, b1, W2, b2, log_Q, log_R
// Output: concat[ theta_hat (8388608), d (8388608), K_star (512) ] fp32
// ============================================================================
extern "C" void kernel_launch(void* const* d_in, const int* in_sizes, int n_in,
                              void* d_out, int out_size)
{
    const float* theta = (const float*)d_in[0];
    const float* x     = (const float*)d_in[1];
    const float* W1    = (const float*)d_in[2];
    const float* b1    = (const float*)d_in[3];
    const float* W2    = (const float*)d_in[4];
    const float* b2    = (const float*)d_in[5];
    const float* lq    = (const float*)d_in[6];
    const float* lr    = (const float*)d_in[7];
    float* out = (float*)d_out;

    const size_t n_main = (size_t)M_ * CH;   // 8388608
    const int write_d = (size_t)out_size >= 2 * n_main;
    const int write_k = (size_t)out_size >= 2 * n_main + CH;

    gemm1_gelu_kernel<<<M_ / 64, 256>>>(x, W1, b1);
    kstar_kernel<<<1, CH>>>(lq, lr, out + 2 * n_main, write_k);
    gemm2_nu_kernel<<<dim3(M_ / 64, CH / 128), 256>>>(W2, b2, theta);
    carry_kernel<<<B_ * NCHUNK, CH>>>();
    combine_kernel<<<B_, CH>>>();
    final_kernel<<<B_ * NCHUNK, CH>>>(theta, out, write_d);
}

// round 8
// speedup vs baseline: 1.1939x; 1.1939x over previous
#include <cuda_runtime.h>
#include <math.h>
#include <stdint.h>

// ---------------------------------------------------------------------------
// Problem constants
// ---------------------------------------------------------------------------
#define B_ 2
#define T_ 8192
#define H_ 16
#define NB_ 32
#define CH 512              // H*NB
#define D_ 1024
#define DH_ 128
#define M_ (B_*T_)          // 16384 rows
#define LCH 64              // scan chunk length
#define NCHUNK (T_/LCH)     // 128 chunks

#define PI_F   3.14159265358979323846f
#define TWOPI_F 6.283185307179586f

typedef unsigned long long u64;

// ---------------------------------------------------------------------------
// Scratch (static device globals; no runtime alloc)
// ---------------------------------------------------------------------------
__device__ float g_hid[(size_t)M_*DH_];         // 8 MB
__device__ float g_nu [(size_t)M_*CH];          // 33.5 MB
__device__ float g_K[CH];
__device__ float g_alpha[CH];
__device__ float g_carry[B_*NCHUNK*CH];         // 512 KB

// ---------------------------------------------------------------------------
// Packed dual-fp32 FMA (FFMA2). Two independent round-to-nearest fp32 FMAs;
// bit-identical to scalar fmaf on each half.
// ---------------------------------------------------------------------------
__device__ __forceinline__ void ffma2(u64& acc, u64 a, u64 b) {
    asm("fma.rn.f32x2 %0, %1, %2, %0;" : "+l"(acc) : "l"(a), "l"(b));
}
__device__ __forceinline__ u64 pack2(float x) {
    u64 r;
    asm("mov.b64 %0, {%1, %1};" : "=l"(r) : "f"(x));
    return r;
}
__device__ __forceinline__ float lo32(u64 v) {
    return __uint_as_float((uint32_t)v);
}
__device__ __forceinline__ float hi32(u64 v) {
    return __uint_as_float((uint32_t)(v >> 32));
}

// ---------------------------------------------------------------------------
// FFMA2 GEMM, BM=64, BN=128, BK=16, 256 threads, micro-tile 4x8 (4x4 pairs).
//   EPI==0: g_hid = gelu(A @ W1 + b1)        A=[M,1024], W1=[1024,128]
//   EPI==1: g_nu  = wrap(pi*tanh(g_hid @ W2 + b2) - theta)   W2=[128,512]
// Global->register prefetch double buffering over K tiles.
// ---------------------------------------------------------------------------
template<int KDIM, int NW, int EPI>
__global__ __launch_bounds__(256) void gemm_ffma2_kernel(
    const float* __restrict__ Ain, const float* __restrict__ W,
    const float* __restrict__ bias, const float* __restrict__ theta)
{
    __shared__ float As[16][68];   // [k][m] padded
    __shared__ float Bs[16][128];  // [k][n]

    const int tid = threadIdx.x;
    const int tx = tid & 15;       // cols tx*8 .. +7
    const int ty = tid >> 4;       // rows ty*4 .. +3
    const int m0 = blockIdx.x * 64;
    const int n0 = blockIdx.y * 128;

    const float* A = (EPI == 0) ? Ain : (const float*)g_hid;

    // A tile: each thread one float4 (row arow, k akq..akq+3)
    const int arow = tid >> 2;          // 0..63
    const int akq  = (tid & 3) * 4;     // 0,4,8,12
    // B tile: each thread 8 floats (k-row bk, n bn..bn+7)
    const int bk = tid >> 4;            // 0..15
    const int bn = (tid & 15) * 8;      // 0..120

    const float* Aptr = A + (size_t)(m0 + arow) * KDIM + akq;
    const float* Wptr = W + (size_t)bk * NW + n0 + bn;

    u64 acc[4][4];
    #pragma unroll
    for (int i = 0; i < 4; i++)
        #pragma unroll
        for (int j = 0; j < 4; j++) acc[i][j] = 0ull;

    // prefetch tile 0
    float4 pa  = *(const float4*)(Aptr);
    float4 pb0 = *(const float4*)(Wptr);
    float4 pb1 = *(const float4*)(Wptr + 4);

    for (int k0 = 0; k0 < KDIM; k0 += 16) {
        // stage current tile to smem
        As[akq + 0][arow] = pa.x;
        As[akq + 1][arow] = pa.y;
        As[akq + 2][arow] = pa.z;
        As[akq + 3][arow] = pa.w;
        *(float4*)&Bs[bk][bn]     = pb0;
        *(float4*)&Bs[bk][bn + 4] = pb1;
        __syncthreads();

        // prefetch next tile while computing
        if (k0 + 16 < KDIM) {
            pa  = *(const float4*)(Aptr + k0 + 16);
            pb0 = *(const float4*)(Wptr + (size_t)(k0 + 16) * NW);
            pb1 = *(const float4*)(Wptr + (size_t)(k0 + 16) * NW + 4);
        }

        #pragma unroll
        for (int kk = 0; kk < 16; kk++) {
            float4 a4 = *(const float4*)&As[kk][ty * 4];
            ulonglong2 b01 = *(const ulonglong2*)&Bs[kk][tx * 8];
            ulonglong2 b23 = *(const ulonglong2*)&Bs[kk][tx * 8 + 4];
            u64 ap0 = pack2(a4.x), ap1 = pack2(a4.y);
            u64 ap2 = pack2(a4.z), ap3 = pack2(a4.w);
            ffma2(acc[0][0], ap0, b01.x); ffma2(acc[0][1], ap0, b01.y);
            ffma2(acc[0][2], ap0, b23.x); ffma2(acc[0][3], ap0, b23.y);
            ffma2(acc[1][0], ap1, b01.x); ffma2(acc[1][1], ap1, b01.y);
            ffma2(acc[1][2], ap1, b23.x); ffma2(acc[1][3], ap1, b23.y);
            ffma2(acc[2][0], ap2, b01.x); ffma2(acc[2][1], ap2, b01.y);
            ffma2(acc[2][2], ap2, b23.x); ffma2(acc[2][3], ap2, b23.y);
            ffma2(acc[3][0], ap3, b01.x); ffma2(acc[3][1], ap3, b01.y);
            ffma2(acc[3][2], ap3, b23.x); ffma2(acc[3][3], ap3, b23.y);
        }
        __syncthreads();
    }

    // epilogue
    #pragma unroll
    for (int i = 0; i < 4; i++) {
        const int m = m0 + ty * 4 + i;
        float v[8];
        #pragma unroll
        for (int j = 0; j < 4; j++) {
            v[2 * j]     = lo32(acc[i][j]);
            v[2 * j + 1] = hi32(acc[i][j]);
        }
        #pragma unroll
        for (int j = 0; j < 8; j++) {
            const int n = n0 + tx * 8 + j;
            if (EPI == 0) {
                float x = v[j] + bias[n];
                g_hid[(size_t)m * DH_ + n] = x * normcdff(x);   // exact GELU
            } else {
                float z = PI_F * tanhf(v[j] + bias[n]);
                float diff = z - theta[(size_t)m * CH + n];
                g_nu[(size_t)m * CH + n] = remainderf(diff, TWOPI_F);
            }
        }
    }
}

// ---------------------------------------------------------------------------
// K* closed-form DARE
// ---------------------------------------------------------------------------
__global__ void kstar_kernel(const float* __restrict__ lq,
                             const float* __restrict__ lr,
                             float* __restrict__ outK, int write_out)
{
    int i = threadIdx.x;
    float Q = expf(lq[i]);
    float R = expf(lr[i]);
    float P_post = 0.5f * (-Q + sqrtf(Q * Q + 4.0f * Q * R));
    float P_pred = P_post + Q;
    float K = P_pred / (P_pred + R);
    g_K[i] = K;
    g_alpha[i] = 1.0f - K;
    if (write_out) outK[i] = K;
}

// ---------------------------------------------------------------------------
// Scan pass A: per-(b, chunk) local carries.  grid = B*NCHUNK, block 512.
// Coalesced: all 512 channels of one t are contiguous.
// ---------------------------------------------------------------------------
__global__ __launch_bounds__(512) void carry_kernel()
{
    const int bx = blockIdx.x;
    const int b = bx / NCHUNK;
    const int j = bx % NCHUNK;
    const int ch = threadIdx.x;
    const float K = g_K[ch];
    const float a = g_alpha[ch];
    const float* nu = g_nu + ((size_t)(b * T_ + j * LCH)) * CH + ch;

    float c = 0.f;
    for (int i0 = 0; i0 < LCH; i0 += 8) {
        float v[8];
        #pragma unroll
        for (int u = 0; u < 8; u++) v[u] = nu[(size_t)(i0 + u) * CH];
        #pragma unroll
        for (int u = 0; u < 8; u++) c = fmaf(a, c, K * v[u]);
    }
    g_carry[(b * NCHUNK + j) * CH + ch] = c;
}

// ---------------------------------------------------------------------------
// Scan pass B: exact carry combine across chunks (factor alpha^LCH).
// Rewrites g_carry[b][j][ch] to hold the carry-IN for chunk j.
// ---------------------------------------------------------------------------
__global__ __launch_bounds__(512) void combine_kernel()
{
    const int b = blockIdx.x;
    const int ch = threadIdx.x;
    float a = g_alpha[ch];
    float aL = a;
    #pragma unroll
    for (int i = 0; i < 6; i++) aL *= aL;   // alpha^64 (LCH=2^6)

    float s = 0.f;
    for (int j0 = 0; j0 < NCHUNK; j0 += 8) {
        float v[8];
        #pragma unroll
        for (int u = 0; u < 8; u++)
            v[u] = g_carry[(b * NCHUNK + j0 + u) * CH + ch];
        #pragma unroll
        for (int u = 0; u < 8; u++) {
            g_carry[(b * NCHUNK + j0 + u) * CH + ch] = s;
            s = fmaf(aL, s, v[u]);
        }
    }
}

// ---------------------------------------------------------------------------
// Scan pass C: final recurrence; write theta_hat and d.
// ---------------------------------------------------------------------------
__global__ __launch_bounds__(512) void final_kernel(
    const float* __restrict__ theta, float* __restrict__ out, int write_d)
{
    const int bx = blockIdx.x;
    const int b = bx / NCHUNK;
    const int j = bx % NCHUNK;
    const int ch = threadIdx.x;
    const float K = g_K[ch];
    const float a = g_alpha[ch];

    float d = g_carry[(b * NCHUNK + j) * CH + ch];
    const size_t base = ((size_t)(b * T_ + j * LCH)) * CH + ch;
    float* outd = out + (size_t)M_ * CH;

    for (int i0 = 0; i0 < LCH; i0 += 4) {
        float v[4], th[4];
        #pragma unroll
        for (int u = 0; u < 4; u++) {
            const size_t idx = base + (size_t)(i0 + u) * CH;
            v[u]  = g_nu[idx];
            th[u] = theta[idx];
        }
        #pragma unroll
        for (int u = 0; u < 4; u++) {
            const size_t idx = base + (size_t)(i0 + u) * CH;
            d = fmaf(a, d, K * v[u]);
            out[idx] = th[u] + d;
            if (write_d) outd[idx] = d;
        }
    }
}

// ---------------------------------------------------------------------------
// Launch.  Inputs: theta_path, content_emb, W1, b1, W2, b2, log_Q, log_R
// Output: concat[ theta_hat (M*CH), d (M*CH), K_star (CH) ] fp32
// ---------------------------------------------------------------------------
extern "C" void kernel_launch(void* const* d_in, const int* in_sizes, int n_in,
                              void* d_out, int out_size)
{
    const float* theta = (const float*)d_in[0];
    const float* x     = (const float*)d_in[1];
    const float* W1    = (const float*)d_in[2];
    const float* b1    = (const float*)d_in[3];
    const float* W2    = (const float*)d_in[4];
    const float* b2    = (const float*)d_in[5];
    const float* lq    = (const float*)d_in[6];
    const float* lr    = (const float*)d_in[7];
    float* out = (float*)d_out;

    const size_t n_main = (size_t)M_ * CH;
    const int write_d = (size_t)out_size >= 2 * n_main;
    const int write_k = (size_t)out_size >= 2 * n_main + CH;

    kstar_kernel<<<1, CH>>>(lq, lr, out + 2 * n_main, write_k);
    gemm_ffma2_kernel<1024, DH_, 0><<<dim3(M_ / 64, 1), 256>>>(x, W1, b1, nullptr);
    gemm_ffma2_kernel<128,  CH,  1><<<dim3(M_ / 64, CH / 128), 256>>>(nullptr, W2, b2, theta);
    carry_kernel<<<B_ * NCHUNK, CH>>>();
    combine_kernel<<<B_, CH>>>();
    final_kernel<<<B_ * NCHUNK, CH>>>(theta, out, write_d);
}

// round 9
// speedup vs baseline: 1.5998x; 1.3399x over previous
#include <cuda_runtime.h>
#include <math.h>
#include <stdint.h>

// ---------------------------------------------------------------------------
// Problem constants
// ---------------------------------------------------------------------------
#define B_ 2
#define T_ 8192
#define H_ 16
#define NB_ 32
#define CH 512              // H*NB
#define D_ 1024
#define DH_ 128
#define M_ (B_*T_)          // 16384 rows
#define LCH 64              // scan chunk length
#define NCHUNK (T_/LCH)     // 128 chunks

#define PI_F   3.14159265358979323846f
#define TWOPI_F 6.283185307179586f

typedef unsigned long long u64;

// ---------------------------------------------------------------------------
// Scratch (static device globals; no runtime alloc)
// ---------------------------------------------------------------------------
__device__ float g_hid[(size_t)M_*DH_];         // 8 MB
__device__ float g_nu [(size_t)M_*CH];          // 33.5 MB
__device__ float g_K[CH];
__device__ float g_alpha[CH];
__device__ float g_carry[B_*NCHUNK*CH];         // 512 KB

// ---------------------------------------------------------------------------
// Packed dual-fp32 FMA (FFMA2): two independent RN fp32 FMAs, bit-identical
// to scalar fmaf per half.
// ---------------------------------------------------------------------------
__device__ __forceinline__ void ffma2(u64& acc, u64 a, u64 b) {
    asm("fma.rn.f32x2 %0, %1, %2, %0;" : "+l"(acc) : "l"(a), "l"(b));
}
__device__ __forceinline__ u64 pack2(float x) {
    u64 r;
    asm("mov.b64 %0, {%1, %1};" : "=l"(r) : "f"(x));
    return r;
}
__device__ __forceinline__ float lo32(u64 v) {
    return __uint_as_float((uint32_t)v);
}
__device__ __forceinline__ float hi32(u64 v) {
    return __uint_as_float((uint32_t)(v >> 32));
}

// ---------------------------------------------------------------------------
// FFMA2 GEMM: BM=128, BN=128, BK=16, 256 threads, 8x8 micro-tile.
//   EPI==0: g_hid = gelu(A @ W1 + b1)                      KDIM=1024, NW=128
//   EPI==1: g_nu  = wrap(pi*tanh(g_hid @ W2 + b2) - theta) KDIM=128,  NW=512
// A staged k-major in SMEM (conflict-free), B staged n-major.
// Ping-pong double buffer, one __syncthreads per K tile.
// Thread (tx,ty): rows {ty*4+0..3, ty*4+64..67}, cols {tx*4+0..3, tx*4+64..67}.
// ---------------------------------------------------------------------------
template<int KDIM, int NW, int EPI>
__global__ __launch_bounds__(256, 1) void gemm_ffma2_kernel(
    const float* __restrict__ Ain, const float* __restrict__ W,
    const float* __restrict__ bias, const float* __restrict__ theta)
{
    __shared__ float As[2][16][132];   // [buf][k][m], padded stride
    __shared__ float Bs[2][16][128];   // [buf][k][n]

    const int tid = threadIdx.x;
    const int tx = tid & 15;
    const int ty = tid >> 4;
    const int m0 = blockIdx.x * 128;
    const int n0 = blockIdx.y * 128;
    constexpr int NC = KDIM / 16;

    const float* A = (EPI == 0) ? Ain : (const float*)g_hid;

    // A load: row = tid&127, k-offset ak = (tid>>7)*8 -> 8 contiguous floats (32B)
    const int arow = tid & 127;
    const int ak   = (tid >> 7) * 8;
    // B load: k-row bkr = tid>>5 (and +8), n = (tid&31)*4 -> float4
    const int bkr = tid >> 5;
    const int bnc = (tid & 31) * 4;

    const float* Ap = A + (size_t)(m0 + arow) * KDIM + ak;
    const float* Wp = W + (size_t)bkr * NW + n0 + bnc;

    u64 acc[8][4];
    #pragma unroll
    for (int i = 0; i < 8; i++)
        #pragma unroll
        for (int j = 0; j < 4; j++) acc[i][j] = 0ull;

    // ---- stage tile 0 ----
    float4 pa0 = *(const float4*)(Ap);
    float4 pa1 = *(const float4*)(Ap + 4);
    float4 pb0 = *(const float4*)(Wp);
    float4 pb1 = *(const float4*)(Wp + (size_t)8 * NW);
    {
        As[0][ak + 0][arow] = pa0.x; As[0][ak + 1][arow] = pa0.y;
        As[0][ak + 2][arow] = pa0.z; As[0][ak + 3][arow] = pa0.w;
        As[0][ak + 4][arow] = pa1.x; As[0][ak + 5][arow] = pa1.y;
        As[0][ak + 6][arow] = pa1.z; As[0][ak + 7][arow] = pa1.w;
        *(float4*)&Bs[0][bkr][bnc]     = pb0;
        *(float4*)&Bs[0][bkr + 8][bnc] = pb1;
    }
    __syncthreads();

    int bi = 0;
    for (int c = 0; c < NC; c++) {
        // prefetch next tile into registers
        if (c + 1 < NC) {
            const int ko = (c + 1) * 16;
            pa0 = *(const float4*)(Ap + ko);
            pa1 = *(const float4*)(Ap + ko + 4);
            pb0 = *(const float4*)(Wp + (size_t)ko * NW);
            pb1 = *(const float4*)(Wp + (size_t)(ko + 8) * NW);
        }

        // compute on buffer bi
        #pragma unroll
        for (int kk = 0; kk < 16; kk++) {
            float4 ar0 = *(const float4*)&As[bi][kk][ty * 4];
            float4 ar1 = *(const float4*)&As[bi][kk][ty * 4 + 64];
            ulonglong2 bp0 = *(const ulonglong2*)&Bs[bi][kk][tx * 4];
            ulonglong2 bp1 = *(const ulonglong2*)&Bs[bi][kk][tx * 4 + 64];
            u64 ap[8];
            ap[0] = pack2(ar0.x); ap[1] = pack2(ar0.y);
            ap[2] = pack2(ar0.z); ap[3] = pack2(ar0.w);
            ap[4] = pack2(ar1.x); ap[5] = pack2(ar1.y);
            ap[6] = pack2(ar1.z); ap[7] = pack2(ar1.w);
            #pragma unroll
            for (int i = 0; i < 8; i++) {
                ffma2(acc[i][0], ap[i], bp0.x);
                ffma2(acc[i][1], ap[i], bp0.y);
                ffma2(acc[i][2], ap[i], bp1.x);
                ffma2(acc[i][3], ap[i], bp1.y);
            }
        }

        // store next tile into the other buffer
        if (c + 1 < NC) {
            const int nb = bi ^ 1;
            As[nb][ak + 0][arow] = pa0.x; As[nb][ak + 1][arow] = pa0.y;
            As[nb][ak + 2][arow] = pa0.z; As[nb][ak + 3][arow] = pa0.w;
            As[nb][ak + 4][arow] = pa1.x; As[nb][ak + 5][arow] = pa1.y;
            As[nb][ak + 6][arow] = pa1.z; As[nb][ak + 7][arow] = pa1.w;
            *(float4*)&Bs[nb][bkr][bnc]     = pb0;
            *(float4*)&Bs[nb][bkr + 8][bnc] = pb1;
        }
        __syncthreads();
        bi ^= 1;
    }

    // ---- epilogue ----
    float4 bv[2];
    bv[0] = *(const float4*)&bias[n0 + tx * 4];
    bv[1] = *(const float4*)&bias[n0 + tx * 4 + 64];

    #pragma unroll
    for (int i = 0; i < 8; i++) {
        const int m = m0 + ty * 4 + ((i < 4) ? i : (60 + i));  // +64 for i>=4
        #pragma unroll
        for (int g = 0; g < 2; g++) {
            const int n = n0 + tx * 4 + g * 64;
            float4 v;
            v.x = lo32(acc[i][2 * g]);     v.y = hi32(acc[i][2 * g]);
            v.z = lo32(acc[i][2 * g + 1]); v.w = hi32(acc[i][2 * g + 1]);
            if (EPI == 0) {
                float x0 = v.x + bv[g].x, x1 = v.y + bv[g].y;
                float x2 = v.z + bv[g].z, x3 = v.w + bv[g].w;
                float4 r;
                r.x = x0 * normcdff(x0); r.y = x1 * normcdff(x1);
                r.z = x2 * normcdff(x2); r.w = x3 * normcdff(x3);
                *(float4*)&g_hid[(size_t)m * DH_ + n] = r;
            } else {
                float4 th = *(const float4*)&theta[(size_t)m * CH + n];
                float4 r;
                r.x = remainderf(PI_F * tanhf(v.x + bv[g].x) - th.x, TWOPI_F);
                r.y = remainderf(PI_F * tanhf(v.y + bv[g].y) - th.y, TWOPI_F);
                r.z = remainderf(PI_F * tanhf(v.z + bv[g].z) - th.z, TWOPI_F);
                r.w = remainderf(PI_F * tanhf(v.w + bv[g].w) - th.w, TWOPI_F);
                *(float4*)&g_nu[(size_t)m * CH + n] = r;
            }
        }
    }
}

// ---------------------------------------------------------------------------
// K* closed-form DARE
// ---------------------------------------------------------------------------
__global__ void kstar_kernel(const float* __restrict__ lq,
                             const float* __restrict__ lr,
                             float* __restrict__ outK, int write_out)
{
    int i = threadIdx.x;
    float Q = expf(lq[i]);
    float R = expf(lr[i]);
    float P_post = 0.5f * (-Q + sqrtf(Q * Q + 4.0f * Q * R));
    float P_pred = P_post + Q;
    float K = P_pred / (P_pred + R);
    g_K[i] = K;
    g_alpha[i] = 1.0f - K;
    if (write_out) outK[i] = K;
}

// ---------------------------------------------------------------------------
// Scan pass A: per-(b, chunk) local carries.  grid = B*NCHUNK, block 512.
// ---------------------------------------------------------------------------
__global__ __launch_bounds__(512) void carry_kernel()
{
    const int bx = blockIdx.x;
    const int b = bx / NCHUNK;
    const int j = bx % NCHUNK;
    const int ch = threadIdx.x;
    const float K = g_K[ch];
    const float a = g_alpha[ch];
    const float* nu = g_nu + ((size_t)(b * T_ + j * LCH)) * CH + ch;

    float c = 0.f;
    for (int i0 = 0; i0 < LCH; i0 += 8) {
        float v[8];
        #pragma unroll
        for (int u = 0; u < 8; u++) v[u] = nu[(size_t)(i0 + u) * CH];
        #pragma unroll
        for (int u = 0; u < 8; u++) c = fmaf(a, c, K * v[u]);
    }
    g_carry[(b * NCHUNK + j) * CH + ch] = c;
}

// ---------------------------------------------------------------------------
// Scan pass B: exact carry combine across chunks (factor alpha^LCH).
// ---------------------------------------------------------------------------
__global__ __launch_bounds__(512) void combine_kernel()
{
    const int b = blockIdx.x;
    const int ch = threadIdx.x;
    float a = g_alpha[ch];
    float aL = a;
    #pragma unroll
    for (int i = 0; i < 6; i++) aL *= aL;   // alpha^64

    float s = 0.f;
    for (int j0 = 0; j0 < NCHUNK; j0 += 8) {
        float v[8];
        #pragma unroll
        for (int u = 0; u < 8; u++)
            v[u] = g_carry[(b * NCHUNK + j0 + u) * CH + ch];
        #pragma unroll
        for (int u = 0; u < 8; u++) {
            g_carry[(b * NCHUNK + j0 + u) * CH + ch] = s;
            s = fmaf(aL, s, v[u]);
        }
    }
}

// ---------------------------------------------------------------------------
// Scan pass C: final recurrence; write theta_hat and d.  8-wide batches.
// ---------------------------------------------------------------------------
__global__ __launch_bounds__(512) void final_kernel(
    const float* __restrict__ theta, float* __restrict__ out, int write_d)
{
    const int bx = blockIdx.x;
    const int b = bx / NCHUNK;
    const int j = bx % NCHUNK;
    const int ch = threadIdx.x;
    const float K = g_K[ch];
    const float a = g_alpha[ch];

    float d = g_carry[(b * NCHUNK + j) * CH + ch];
    const size_t base = ((size_t)(b * T_ + j * LCH)) * CH + ch;
    float* outd = out + (size_t)M_ * CH;

    for (int i0 = 0; i0 < LCH; i0 += 8) {
        float v[8], th[8];
        #pragma unroll
        for (int u = 0; u < 8; u++) {
            const size_t idx = base + (size_t)(i0 + u) * CH;
            v[u]  = g_nu[idx];
            th[u] = theta[idx];
        }
        #pragma unroll
        for (int u = 0; u < 8; u++) {
            const size_t idx = base + (size_t)(i0 + u) * CH;
            d = fmaf(a, d, K * v[u]);
            out[idx] = th[u] + d;
            if (write_d) outd[idx] = d;
        }
    }
}

// ---------------------------------------------------------------------------
// Launch.  Inputs: theta_path, content_emb, W1, b1, W2, b2, log_Q, log_R
// Output: concat[ theta_hat (M*CH), d (M*CH), K_star (CH) ] fp32
// ---------------------------------------------------------------------------
extern "C" void kernel_launch(void* const* d_in, const int* in_sizes, int n_in,
                              void* d_out, int out_size)
{
    const float* theta = (const float*)d_in[0];
    const float* x     = (const float*)d_in[1];
    const float* W1    = (const float*)d_in[2];
    const float* b1    = (const float*)d_in[3];
    const float* W2    = (const float*)d_in[4];
    const float* b2    = (const float*)d_in[5];
    const float* lq    = (const float*)d_in[6];
    const float* lr    = (const float*)d_in[7];
    float* out = (float*)d_out;

    const size_t n_main = (size_t)M_ * CH;
    const int write_d = (size_t)out_size >= 2 * n_main;
    const int write_k = (size_t)out_size >= 2 * n_main + CH;

    kstar_kernel<<<1, CH>>>(lq, lr, out + 2 * n_main, write_k);
    gemm_ffma2_kernel<1024, DH_, 0><<<dim3(M_ / 128, 1), 256>>>(x, W1, b1, nullptr);
    gemm_ffma2_kernel<128,  CH,  1><<<dim3(M_ / 128, CH / 128), 256>>>(nullptr, W2, b2, theta);
    carry_kernel<<<B_ * NCHUNK, CH>>>();
    combine_kernel<<<B_, CH>>>();
    final_kernel<<<B_ * NCHUNK, CH>>>(theta, out, write_d);
}